// round 1
// baseline (speedup 1.0000x reference)
#include <cuda_runtime.h>
#include <math.h>

// Problem constants
#define BB   16      // batch
#define KK   4       // beam
#define RR   64      // BB*KK rows
#define SS   512     // encoder seq
#define DD   512     // model dim
#define VV   32000   // vocab
#define TT   64      // max len
#define SOS_ 1
#define EOS_ 2
#define PAD_ 0
#define NEG_ (-1e9f)

// -------- device state --------
__device__ float g_encK[BB * SS * DD];      // 16.8 MB
__device__ float g_e[RR * DD];
__device__ float g_q[RR * DD];
__device__ float g_h[RR * DD];
__device__ float g_logits[RR * VV];         // 8.2 MB
__device__ float g_top4v[RR * 4];
__device__ int   g_top4i[RR * 4];
__device__ float g_lse[RR];
__device__ int   g_seqs[2][RR * TT];
__device__ float g_scores[RR];
__device__ int   g_finished[RR];
__device__ int   g_last[RR];

// ============ generic tiled fp32 GEMM: C[M,N] = A[M,K]*B[K,N] (+bias) ============
// M,N multiples of 64; K multiple of 32 (all exact for our shapes).
#define BM 64
#define BN 64
#define BKc 32
__global__ __launch_bounds__(256) void gemm_kernel(
    const float* __restrict__ A, const float* __restrict__ B,
    const float* __restrict__ bias, float* __restrict__ C,
    int M, int N, int Kd)
{
    __shared__ float As[BKc][BM + 1];
    __shared__ float Bs[BKc][BN];
    const int tid = threadIdx.x;
    const int n0 = blockIdx.x * BN;
    const int m0 = blockIdx.y * BM;
    const int tc = tid & 15;   // 0..15 (col group)
    const int tr = tid >> 4;   // 0..15 (row group)

    float acc[4][4];
#pragma unroll
    for (int i = 0; i < 4; i++)
#pragma unroll
        for (int j = 0; j < 4; j++) acc[i][j] = 0.f;

    for (int k0 = 0; k0 < Kd; k0 += BKc) {
#pragma unroll
        for (int l = tid; l < BM * BKc; l += 256) {
            int m = l >> 5, k = l & 31;
            As[k][m] = A[(size_t)(m0 + m) * Kd + (k0 + k)];
        }
#pragma unroll
        for (int l = tid; l < BKc * BN; l += 256) {
            int n = l & 63, k = l >> 6;
            Bs[k][n] = B[(size_t)(k0 + k) * N + (n0 + n)];
        }
        __syncthreads();
#pragma unroll
        for (int kk = 0; kk < BKc; kk++) {
            float a[4], bb[4];
#pragma unroll
            for (int i = 0; i < 4; i++) a[i] = As[kk][tr * 4 + i];
#pragma unroll
            for (int j = 0; j < 4; j++) bb[j] = Bs[kk][tc * 4 + j];
#pragma unroll
            for (int i = 0; i < 4; i++)
#pragma unroll
                for (int j = 0; j < 4; j++) acc[i][j] += a[i] * bb[j];
        }
        __syncthreads();
    }
#pragma unroll
    for (int i = 0; i < 4; i++) {
        int m = m0 + tr * 4 + i;
#pragma unroll
        for (int j = 0; j < 4; j++) {
            int n = n0 + tc * 4 + j;
            float v = acc[i][j];
            if (bias) v += bias[n];
            C[(size_t)m * N + n] = v;
        }
    }
}

// ============ small kernels ============
__global__ void init_last_kernel() {
    g_last[threadIdx.x] = SOS_;
}

__global__ void gather_kernel(const float* __restrict__ emb) {
    int row = blockIdx.x;
    int tok = g_last[row];
    g_e[row * DD + threadIdx.x] = emb[(size_t)tok * DD + threadIdx.x];
}

// attention + softmax + context + h = e + ctx  (one block per (b,k) row)
__global__ __launch_bounds__(256) void attn_kernel(
    const float* __restrict__ enc, const int* __restrict__ lens)
{
    const int row = blockIdx.x;
    const int b = row >> 2;
    __shared__ float qs[SS];
    __shared__ float att[SS];
    __shared__ float red[16];
    const int tid = threadIdx.x, lane = tid & 31, w = tid >> 5;

    for (int i = tid; i < DD; i += 256) qs[i] = g_q[row * DD + i];
    __syncthreads();

    const int len = lens[b];
    const float scale = 0.04419417382415922f; // 1/sqrt(512)

    // att[s] = (q . encK[b,s]) * scale, masked  (warp-per-s dot products)
    for (int s = w; s < SS; s += 8) {
        const float* kr = g_encK + ((size_t)b * SS + s) * DD;
        float acc = 0.f;
#pragma unroll 4
        for (int d = lane; d < DD; d += 32) acc += qs[d] * kr[d];
#pragma unroll
        for (int o = 16; o > 0; o >>= 1) acc += __shfl_xor_sync(0xffffffffu, acc, o);
        if (lane == 0) att[s] = (s < len) ? acc * scale : NEG_;
    }
    __syncthreads();

    // block max
    float m = -3.4e38f;
    for (int s = tid; s < SS; s += 256) m = fmaxf(m, att[s]);
#pragma unroll
    for (int o = 16; o > 0; o >>= 1) m = fmaxf(m, __shfl_xor_sync(0xffffffffu, m, o));
    if (lane == 0) red[w] = m;
    __syncthreads();
    if (tid == 0) {
        float mm = red[0];
        for (int i = 1; i < 8; i++) mm = fmaxf(mm, red[i]);
        red[8] = mm;
    }
    __syncthreads();
    m = red[8];
    __syncthreads();

    // exp + sum
    float sum = 0.f;
    for (int s = tid; s < SS; s += 256) {
        float p = expf(att[s] - m);
        att[s] = p;
        sum += p;
    }
#pragma unroll
    for (int o = 16; o > 0; o >>= 1) sum += __shfl_xor_sync(0xffffffffu, sum, o);
    if (lane == 0) red[w] = sum;
    __syncthreads();
    if (tid == 0) {
        float ss = 0.f;
        for (int i = 0; i < 8; i++) ss += red[i];
        red[9] = ss;
    }
    __syncthreads();
    const float inv = 1.0f / red[9];
    __syncthreads();

    // ctx[d] = sum_s p[s]*enc[b,s,d]; h = e + ctx
    const float* er = enc + (size_t)b * SS * DD;
    const int d0 = tid, d1 = tid + 256;
    float c0 = 0.f, c1 = 0.f;
#pragma unroll 4
    for (int s = 0; s < SS; s++) {
        float p = att[s];
        c0 += p * er[(size_t)s * DD + d0];
        c1 += p * er[(size_t)s * DD + d1];
    }
    g_h[row * DD + d0] = g_e[row * DD + d0] + c0 * inv;
    g_h[row * DD + d1] = g_e[row * DD + d1] + c1 * inv;
}

// ---- top4 + logsumexp per row (stable tie-break: lower index wins on ties) ----
__device__ __forceinline__ bool better_vi(float v1, int i1, float v2, int i2) {
    return (v1 > v2) || (v1 == v2 && i1 < i2);
}

__global__ __launch_bounds__(256) void top4_lse_kernel() {
    const int row = blockIdx.x;
    const float* __restrict__ L = g_logits + (size_t)row * VV;
    __shared__ float sv[256 * 4];
    __shared__ int   si[256 * 4];
    __shared__ float ssum[8];
    const int tid = threadIdx.x, lane = tid & 31, w = tid >> 5;

    float v[4] = {-3.4e38f, -3.4e38f, -3.4e38f, -3.4e38f};
    int   ix[4] = {0x7fffffff, 0x7fffffff, 0x7fffffff, 0x7fffffff};
    for (int j = tid; j < VV; j += 256) {
        float x = L[j];
        if (better_vi(x, j, v[3], ix[3])) {
            v[3] = x; ix[3] = j;
#pragma unroll
            for (int p = 3; p > 0; p--) {
                if (better_vi(v[p], ix[p], v[p - 1], ix[p - 1])) {
                    float tv = v[p]; v[p] = v[p - 1]; v[p - 1] = tv;
                    int ti = ix[p]; ix[p] = ix[p - 1]; ix[p - 1] = ti;
                }
            }
        }
    }
#pragma unroll
    for (int p = 0; p < 4; p++) { sv[tid * 4 + p] = v[p]; si[tid * 4 + p] = ix[p]; }
    __syncthreads();

    // tree merge of sorted-desc 4-lists
    for (int off = 128; off > 0; off >>= 1) {
        if (tid < off) {
            float av[4], bv[4]; int ai[4], bi[4];
#pragma unroll
            for (int p = 0; p < 4; p++) {
                av[p] = sv[tid * 4 + p];          ai[p] = si[tid * 4 + p];
                bv[p] = sv[(tid + off) * 4 + p];  bi[p] = si[(tid + off) * 4 + p];
            }
            int pa = 0, pb = 0;
            float ov[4]; int oi[4];
#pragma unroll
            for (int t = 0; t < 4; t++) {
                bool takeA = (pb >= 4) || (pa < 4 && better_vi(av[pa], ai[pa], bv[pb], bi[pb]));
                if (takeA) { ov[t] = av[pa]; oi[t] = ai[pa]; pa++; }
                else       { ov[t] = bv[pb]; oi[t] = bi[pb]; pb++; }
            }
#pragma unroll
            for (int p = 0; p < 4; p++) { sv[tid * 4 + p] = ov[p]; si[tid * 4 + p] = oi[p]; }
        }
        __syncthreads();
    }

    if (tid == 0) {
#pragma unroll
        for (int p = 0; p < 4; p++) {
            g_top4v[row * 4 + p] = sv[p];
            g_top4i[row * 4 + p] = si[p];
        }
    }
    const float mx = sv[0];
    __syncthreads();

    // pass 2: logsumexp
    float s = 0.f;
    for (int j = tid; j < VV; j += 256) s += expf(L[j] - mx);
#pragma unroll
    for (int o = 16; o > 0; o >>= 1) s += __shfl_xor_sync(0xffffffffu, s, o);
    if (lane == 0) ssum[w] = s;
    __syncthreads();
    if (tid == 0) {
        float tot = 0.f;
        for (int i = 0; i < 8; i++) tot += ssum[i];
        g_lse[row] = mx + logf(tot);
    }
}

// ---- step 1: expand SOS into top-K beams ----
__global__ void init_combine_kernel() {
    const int b = blockIdx.x, tid = threadIdx.x;  // 64 threads
    __shared__ int toks[4];
    __shared__ float sc[4];
    if (tid == 0) {
        int r = b * KK;  // row k=0
        float lse = g_lse[r];
        for (int k = 0; k < 4; k++) {
            sc[k] = g_top4v[r * 4 + k] - lse;
            toks[k] = g_top4i[r * 4 + k];
        }
    }
    __syncthreads();
    for (int k = 0; k < 4; k++) {
        int val = (tid == 0) ? SOS_ : ((tid == 1) ? toks[k] : PAD_);
        g_seqs[0][(b * KK + k) * TT + tid] = val;
    }
    if (tid < 4) {
        g_scores[b * KK + tid] = sc[tid];
        g_finished[b * KK + tid] = (toks[tid] == EOS_) ? 1 : 0;
        g_last[b * KK + tid] = toks[tid];
    }
}

// ---- per-step beam combine (top4 over beam^2 with finished/pad_delta semantics) ----
__global__ void combine_kernel(int t, int srcbuf) {
    const int b = blockIdx.x, tid = threadIdx.x;  // 64 threads
    __shared__ float total[16];
    __shared__ int   candv[16];
    __shared__ int nbeam[4], ntok[4], nfin[4];
    __shared__ float nsc[4];
    if (tid == 0) {
        for (int k = 0; k < 4; k++) {
            int r = b * KK + k;
            bool fin = (g_finished[r] != 0);
            float lse = g_lse[r];
            float sc = g_scores[r];
            for (int j = 0; j < 4; j++) {
                float lp; int vtok;
                if (fin) { lp = (j == 0) ? 0.f : NEG_; vtok = PAD_; }
                else { lp = g_top4v[r * 4 + j] - lse; vtok = g_top4i[r * 4 + j]; }
                total[k * 4 + j] = sc + lp;
                candv[k * 4 + j] = vtok;
            }
        }
        bool used[16];
        for (int i = 0; i < 16; i++) used[i] = false;
        for (int p = 0; p < 4; p++) {
            int biq = -1; float bvq = -3.4e38f;
            for (int i = 0; i < 16; i++) {
                if (!used[i] && total[i] > bvq) { bvq = total[i]; biq = i; }
            }
            used[biq] = true;
            nbeam[p] = biq >> 2;
            ntok[p] = candv[biq];
            nsc[p] = bvq;
        }
        for (int p = 0; p < 4; p++)
            nfin[p] = (g_finished[b * KK + nbeam[p]] != 0 || ntok[p] == EOS_) ? 1 : 0;
    }
    __syncthreads();
    const int* src = g_seqs[srcbuf];
    int* dst = g_seqs[srcbuf ^ 1];
    for (int k = 0; k < 4; k++) {
        int x = src[(b * KK + nbeam[k]) * TT + tid];
        dst[(b * KK + k) * TT + tid] = (tid == t) ? ntok[k] : x;
    }
    if (tid < 4) {
        g_scores[b * KK + tid] = nsc[tid];
        g_finished[b * KK + tid] = nfin[tid];
        g_last[b * KK + tid] = ntok[tid];
    }
}

// ---- final: argmax beam per batch, write best_seq (as float) + best_score ----
__global__ void finalize_kernel(float* out, int out_size, int srcbuf) {
    const int b = blockIdx.x, tid = threadIdx.x;  // 64 threads
    __shared__ int bbk;
    __shared__ float bbs;
    if (tid == 0) {
        int bi = 0; float bv = g_scores[b * KK];
        for (int k = 1; k < 4; k++) {
            if (g_scores[b * KK + k] > bv) { bv = g_scores[b * KK + k]; bi = k; }
        }
        bbk = bi; bbs = bv;
    }
    __syncthreads();
    if (out_size == BB) {  // scores only
        if (tid == 0) out[b] = bbs;
        return;
    }
    int idx = b * TT + tid;
    if (idx < out_size)
        out[idx] = (float)g_seqs[srcbuf][(b * KK + bbk) * TT + tid];
    if (tid == 0 && BB * TT + b < out_size)
        out[BB * TT + b] = bbs;
}

// ============ host launcher ============
extern "C" void kernel_launch(void* const* d_in, const int* in_sizes, int n_in,
                              void* d_out, int out_size)
{
    const float* enc = (const float*)d_in[0];
    const int*   lens = (const int*)d_in[1];
    const float* emb = (const float*)d_in[2];
    const float* Wq  = (const float*)d_in[3];
    const float* Wk  = (const float*)d_in[4];
    const float* Wfc = (const float*)d_in[5];
    const float* bfc = (const float*)d_in[6];

    float *p_encK, *p_e, *p_q, *p_h, *p_logits;
    cudaGetSymbolAddress((void**)&p_encK, g_encK);
    cudaGetSymbolAddress((void**)&p_e, g_e);
    cudaGetSymbolAddress((void**)&p_q, g_q);
    cudaGetSymbolAddress((void**)&p_h, g_h);
    cudaGetSymbolAddress((void**)&p_logits, g_logits);

    // encK = enc @ W_k   (8192 x 512 x 512)
    {
        dim3 grid(DD / BN, (BB * SS) / BM);
        gemm_kernel<<<grid, 256>>>(enc, Wk, nullptr, p_encK, BB * SS, DD, DD);
    }

    // ---- step 1 (SOS for all rows) ----
    init_last_kernel<<<1, RR>>>();
    gather_kernel<<<RR, DD>>>(emb);
    {
        dim3 grid(DD / BN, RR / BM);
        gemm_kernel<<<grid, 256>>>(p_e, Wq, nullptr, p_q, RR, DD, DD);
    }
    attn_kernel<<<RR, 256>>>(enc, lens);
    {
        dim3 grid(VV / BN, RR / BM);
        gemm_kernel<<<grid, 256>>>(p_h, Wfc, bfc, p_logits, RR, VV, DD);
    }
    top4_lse_kernel<<<RR, 256>>>();
    init_combine_kernel<<<BB, TT>>>();

    // ---- steps t = 2..63 ----
    for (int t = 2; t < TT; t++) {
        gather_kernel<<<RR, DD>>>(emb);
        {
            dim3 grid(DD / BN, RR / BM);
            gemm_kernel<<<grid, 256>>>(p_e, Wq, nullptr, p_q, RR, DD, DD);
        }
        attn_kernel<<<RR, 256>>>(enc, lens);
        {
            dim3 grid(VV / BN, RR / BM);
            gemm_kernel<<<grid, 256>>>(p_h, Wfc, bfc, p_logits, RR, VV, DD);
        }
        top4_lse_kernel<<<RR, 256>>>();
        int srcbuf = t & 1;
        combine_kernel<<<BB, TT>>>(t, srcbuf);
    }

    // after t=63 (odd), last combine wrote buffer 0
    finalize_kernel<<<BB, TT>>>((float*)d_out, out_size, 0);
}

// round 3
// speedup vs baseline: 1.5726x; 1.5726x over previous
#include <cuda_runtime.h>
#include <math.h>

// Problem constants
#define BB   16      // batch
#define KK   4       // beam
#define RR   64      // BB*KK rows
#define SS   512     // encoder seq
#define DD   512     // model dim
#define VV   32000   // vocab
#define TT   64      // max len
#define SOS_ 1
#define EOS_ 2
#define PAD_ 0
#define NEG_ (-1e9f)

// -------- device state --------
__device__ float g_encK[BB * SS * DD];      // 16.8 MB
__device__ float g_h[RR * DD];
__device__ float g_logits[RR * VV];         // 8.2 MB
__device__ float g_top4v[RR * 4];
__device__ int   g_top4i[RR * 4];
__device__ float g_lse[RR];
__device__ int   g_seqs[2][RR * TT];
__device__ float g_scores[RR];
__device__ int   g_finished[RR];
__device__ int   g_last[RR];

// ---------------- packed f32x2 helpers ----------------
__device__ __forceinline__ void ffma2(unsigned long long& d,
                                      unsigned long long a,
                                      unsigned long long b) {
    asm("fma.rn.f32x2 %0, %1, %2, %0;" : "+l"(d) : "l"(a), "l"(b));
}
__device__ __forceinline__ unsigned long long dup2(float x) {
    unsigned long long r;
    asm("mov.b64 %0, {%1, %1};" : "=l"(r) : "f"(x));
    return r;
}
__device__ __forceinline__ void unpack2(unsigned long long v, float& lo, float& hi) {
    asm("mov.b64 {%0, %1}, %2;" : "=f"(lo), "=f"(hi) : "l"(v));
}

// ============ FFMA2 skinny GEMM: C[M,N] = A[M,K]*B[K,N] (+bias) ============
// Block tile 64x64, K-step 32, 128 threads. Thread: 8 rows (4 packed pairs) x 4 cols.
// M mult of 64, N mult of 64, K mult of 32.
#define GTM 64
#define GTN 64
#define GTK 32
#define ASTRIDE 66   // padded, even (keeps 8B alignment for b64 loads)

__global__ __launch_bounds__(128) void gemm2_kernel(
    const float* __restrict__ A, const float* __restrict__ B,
    const float* __restrict__ bias, float* __restrict__ C,
    int M, int N, int Kd)
{
    __shared__ __align__(16) float As[GTK][ASTRIDE];  // transposed: As[k][m]
    __shared__ __align__(16) float Bs[GTK][GTN];
    const int tid = threadIdx.x;
    const int n0 = blockIdx.x * GTN;
    const int m0 = blockIdx.y * GTM;
    const int tc = tid & 15;   // 16 col groups * 4 cols
    const int tr = tid >> 4;   // 8 row groups * 8 rows

    unsigned long long acc[4][4];
#pragma unroll
    for (int i = 0; i < 4; i++)
#pragma unroll
        for (int j = 0; j < 4; j++) acc[i][j] = 0ull;

#pragma unroll 2
    for (int k0 = 0; k0 < Kd; k0 += GTK) {
        // load A tile (64x32): 4 float4 per thread, store transposed
#pragma unroll
        for (int i = 0; i < 4; i++) {
            int s = tid + i * 128;       // 0..511 float4 slots
            int m = s >> 3;              // 0..63
            int kq = (s & 7) * 4;        // 0..28
            float4 v = *(const float4*)(A + (size_t)(m0 + m) * Kd + k0 + kq);
            As[kq + 0][m] = v.x;
            As[kq + 1][m] = v.y;
            As[kq + 2][m] = v.z;
            As[kq + 3][m] = v.w;
        }
        // load B tile (32x64): 4 float4 per thread
#pragma unroll
        for (int i = 0; i < 4; i++) {
            int s = tid + i * 128;       // 0..511 float4 slots
            int k = s >> 4;              // 0..31
            int n4 = (s & 15) * 4;       // 0..60
            *(float4*)&Bs[k][n4] = *(const float4*)(B + (size_t)(k0 + k) * N + n0 + n4);
        }
        __syncthreads();
#pragma unroll
        for (int kk = 0; kk < GTK; kk++) {
            unsigned long long a[4];
#pragma unroll
            for (int i = 0; i < 4; i++)
                a[i] = *(const unsigned long long*)&As[kk][tr * 8 + i * 2];
            float4 bq = *(const float4*)&Bs[kk][tc * 4];
            unsigned long long bd[4];
            bd[0] = dup2(bq.x); bd[1] = dup2(bq.y);
            bd[2] = dup2(bq.z); bd[3] = dup2(bq.w);
#pragma unroll
            for (int i = 0; i < 4; i++)
#pragma unroll
                for (int j = 0; j < 4; j++)
                    ffma2(acc[i][j], a[i], bd[j]);
        }
        __syncthreads();
    }

    // epilogue
#pragma unroll
    for (int i = 0; i < 4; i++) {
        float lo[4], hi[4];
#pragma unroll
        for (int j = 0; j < 4; j++) unpack2(acc[i][j], lo[j], hi[j]);
        int r0 = m0 + tr * 8 + i * 2;
        int c0 = n0 + tc * 4;
        if (bias) {
#pragma unroll
            for (int j = 0; j < 4; j++) {
                float bv = bias[c0 + j];
                lo[j] += bv; hi[j] += bv;
            }
        }
        *(float4*)(C + (size_t)r0 * N + c0)       = make_float4(lo[0], lo[1], lo[2], lo[3]);
        *(float4*)(C + (size_t)(r0 + 1) * N + c0) = make_float4(hi[0], hi[1], hi[2], hi[3]);
    }
}

// ============ small kernels ============
__global__ void init_last_kernel() {
    g_last[threadIdx.x] = SOS_;
}

// fused: gather e -> q = e@Wq -> attention -> softmax -> ctx -> h = e + ctx
// one block (512 thr) per beam row
__global__ __launch_bounds__(512) void prep_kernel(
    const float* __restrict__ enc, const int* __restrict__ lens,
    const float* __restrict__ emb, const float* __restrict__ Wq)
{
    const int row = blockIdx.x;
    const int b = row >> 2;
    __shared__ float es[DD];
    __shared__ float qs[DD];
    __shared__ float att[SS];
    __shared__ float red[18];
    const int tid = threadIdx.x, lane = tid & 31, w = tid >> 5;  // 16 warps

    const int tok = g_last[row];
    es[tid] = emb[(size_t)tok * DD + tid];
    __syncthreads();

    // q[c] = sum_d e[d] * Wq[d][c]
    {
        float qv = 0.f;
#pragma unroll 8
        for (int d = 0; d < DD; d++) qv += es[d] * Wq[(size_t)d * DD + tid];
        qs[tid] = qv;
    }
    __syncthreads();

    const int len = lens[b];
    const float scale = 0.04419417382415922f; // 1/sqrt(512)

    // att[s] = (q . encK[b,s]) * scale, masked  (warp-per-s)
    for (int s = w; s < SS; s += 16) {
        const float* kr = g_encK + ((size_t)b * SS + s) * DD;
        float acc = 0.f;
#pragma unroll 4
        for (int d = lane; d < DD; d += 32) acc += qs[d] * kr[d];
#pragma unroll
        for (int o = 16; o > 0; o >>= 1) acc += __shfl_xor_sync(0xffffffffu, acc, o);
        if (lane == 0) att[s] = (s < len) ? acc * scale : NEG_;
    }
    __syncthreads();

    // softmax over att (512 elems, 1 per thread)
    float x = att[tid];
    float m = x;
#pragma unroll
    for (int o = 16; o > 0; o >>= 1) m = fmaxf(m, __shfl_xor_sync(0xffffffffu, m, o));
    if (lane == 0) red[w] = m;
    __syncthreads();
    if (tid == 0) {
        float mm = red[0];
        for (int i = 1; i < 16; i++) mm = fmaxf(mm, red[i]);
        red[16] = mm;
    }
    __syncthreads();
    m = red[16];
    float p = expf(x - m);
    att[tid] = p;
    float s = p;
#pragma unroll
    for (int o = 16; o > 0; o >>= 1) s += __shfl_xor_sync(0xffffffffu, s, o);
    if (lane == 0) red[w] = s;
    __syncthreads();
    if (tid == 0) {
        float ss = 0.f;
        for (int i = 0; i < 16; i++) ss += red[i];
        red[17] = 1.0f / ss;
    }
    __syncthreads();
    const float inv = red[17];

    // ctx[d] = sum_s p[s]*enc[b,s,d]; h = e + ctx/sum
    const float* er = enc + (size_t)b * SS * DD;
    float c = 0.f;
#pragma unroll 4
    for (int ss2 = 0; ss2 < SS; ss2++) c += att[ss2] * er[(size_t)ss2 * DD + tid];
    g_h[row * DD + tid] = es[tid] + c * inv;
}

// ---- top4 + logsumexp per row (stable tie-break: lower index wins) ----
__device__ __forceinline__ bool better_vi(float v1, int i1, float v2, int i2) {
    return (v1 > v2) || (v1 == v2 && i1 < i2);
}

__global__ __launch_bounds__(512) void top4_lse_kernel() {
    const int row = blockIdx.x;
    const float* __restrict__ L = g_logits + (size_t)row * VV;
    __shared__ float sv[512 * 4];
    __shared__ int   si[512 * 4];
    __shared__ float ssum[16];
    const int tid = threadIdx.x, lane = tid & 31, w = tid >> 5;

    float v[4] = {-3.4e38f, -3.4e38f, -3.4e38f, -3.4e38f};
    int   ix[4] = {0x7fffffff, 0x7fffffff, 0x7fffffff, 0x7fffffff};
    for (int j = tid; j < VV; j += 512) {
        float x = L[j];
        if (better_vi(x, j, v[3], ix[3])) {
            v[3] = x; ix[3] = j;
#pragma unroll
            for (int p = 3; p > 0; p--) {
                if (better_vi(v[p], ix[p], v[p - 1], ix[p - 1])) {
                    float tv = v[p]; v[p] = v[p - 1]; v[p - 1] = tv;
                    int ti = ix[p]; ix[p] = ix[p - 1]; ix[p - 1] = ti;
                }
            }
        }
    }
#pragma unroll
    for (int p = 0; p < 4; p++) { sv[tid * 4 + p] = v[p]; si[tid * 4 + p] = ix[p]; }
    __syncthreads();

    for (int off = 256; off > 0; off >>= 1) {
        if (tid < off) {
            float av[4], bv[4]; int ai[4], bi[4];
#pragma unroll
            for (int p = 0; p < 4; p++) {
                av[p] = sv[tid * 4 + p];          ai[p] = si[tid * 4 + p];
                bv[p] = sv[(tid + off) * 4 + p];  bi[p] = si[(tid + off) * 4 + p];
            }
            int pa = 0, pb = 0;
            float ov[4]; int oi[4];
#pragma unroll
            for (int t = 0; t < 4; t++) {
                bool takeA = (pb >= 4) || (pa < 4 && better_vi(av[pa], ai[pa], bv[pb], bi[pb]));
                if (takeA) { ov[t] = av[pa]; oi[t] = ai[pa]; pa++; }
                else       { ov[t] = bv[pb]; oi[t] = bi[pb]; pb++; }
            }
#pragma unroll
            for (int p = 0; p < 4; p++) { sv[tid * 4 + p] = ov[p]; si[tid * 4 + p] = oi[p]; }
        }
        __syncthreads();
    }

    if (tid == 0) {
#pragma unroll
        for (int p = 0; p < 4; p++) {
            g_top4v[row * 4 + p] = sv[p];
            g_top4i[row * 4 + p] = si[p];
        }
    }
    const float mx = sv[0];
    __syncthreads();

    float s = 0.f;
    for (int j = tid; j < VV; j += 512) s += expf(L[j] - mx);
#pragma unroll
    for (int o = 16; o > 0; o >>= 1) s += __shfl_xor_sync(0xffffffffu, s, o);
    if (lane == 0) ssum[w] = s;
    __syncthreads();
    if (tid == 0) {
        float tot = 0.f;
        for (int i = 0; i < 16; i++) tot += ssum[i];
        g_lse[row] = mx + logf(tot);
    }
}

// ---- step 1: expand SOS into top-K beams ----
__global__ void init_combine_kernel() {
    const int b = blockIdx.x, tid = threadIdx.x;  // 64 threads
    __shared__ int toks[4];
    __shared__ float sc[4];
    if (tid == 0) {
        int r = b * KK;  // row k=0
        float lse = g_lse[r];
        for (int k = 0; k < 4; k++) {
            sc[k] = g_top4v[r * 4 + k] - lse;
            toks[k] = g_top4i[r * 4 + k];
        }
    }
    __syncthreads();
    for (int k = 0; k < 4; k++) {
        int val = (tid == 0) ? SOS_ : ((tid == 1) ? toks[k] : PAD_);
        g_seqs[0][(b * KK + k) * TT + tid] = val;
    }
    if (tid < 4) {
        g_scores[b * KK + tid] = sc[tid];
        g_finished[b * KK + tid] = (toks[tid] == EOS_) ? 1 : 0;
        g_last[b * KK + tid] = toks[tid];
    }
}

// ---- per-step beam combine ----
__global__ void combine_kernel(int t, int srcbuf) {
    const int b = blockIdx.x, tid = threadIdx.x;  // 64 threads
    __shared__ float total[16];
    __shared__ int   candv[16];
    __shared__ int nbeam[4], ntok[4], nfin[4];
    __shared__ float nsc[4];
    if (tid == 0) {
        for (int k = 0; k < 4; k++) {
            int r = b * KK + k;
            bool fin = (g_finished[r] != 0);
            float lse = g_lse[r];
            float sc = g_scores[r];
            for (int j = 0; j < 4; j++) {
                float lp; int vtok;
                if (fin) { lp = (j == 0) ? 0.f : NEG_; vtok = PAD_; }
                else { lp = g_top4v[r * 4 + j] - lse; vtok = g_top4i[r * 4 + j]; }
                total[k * 4 + j] = sc + lp;
                candv[k * 4 + j] = vtok;
            }
        }
        bool used[16];
        for (int i = 0; i < 16; i++) used[i] = false;
        for (int p = 0; p < 4; p++) {
            int biq = -1; float bvq = -3.4e38f;
            for (int i = 0; i < 16; i++) {
                if (!used[i] && total[i] > bvq) { bvq = total[i]; biq = i; }
            }
            used[biq] = true;
            nbeam[p] = biq >> 2;
            ntok[p] = candv[biq];
            nsc[p] = bvq;
        }
        for (int p = 0; p < 4; p++)
            nfin[p] = (g_finished[b * KK + nbeam[p]] != 0 || ntok[p] == EOS_) ? 1 : 0;
    }
    __syncthreads();
    const int* src = g_seqs[srcbuf];
    int* dst = g_seqs[srcbuf ^ 1];
    for (int k = 0; k < 4; k++) {
        int x = src[(b * KK + nbeam[k]) * TT + tid];
        dst[(b * KK + k) * TT + tid] = (tid == t) ? ntok[k] : x;
    }
    if (tid < 4) {
        g_scores[b * KK + tid] = nsc[tid];
        g_finished[b * KK + tid] = nfin[tid];
        g_last[b * KK + tid] = ntok[tid];
    }
}

// ---- final: argmax beam per batch ----
__global__ void finalize_kernel(float* out, int out_size, int srcbuf) {
    const int b = blockIdx.x, tid = threadIdx.x;  // 64 threads
    __shared__ int bbk;
    __shared__ float bbs;
    if (tid == 0) {
        int bi = 0; float bv = g_scores[b * KK];
        for (int k = 1; k < 4; k++) {
            if (g_scores[b * KK + k] > bv) { bv = g_scores[b * KK + k]; bi = k; }
        }
        bbk = bi; bbs = bv;
    }
    __syncthreads();
    if (out_size == BB) {
        if (tid == 0) out[b] = bbs;
        return;
    }
    int idx = b * TT + tid;
    if (idx < out_size)
        out[idx] = (float)g_seqs[srcbuf][(b * KK + bbk) * TT + tid];
    if (tid == 0 && BB * TT + b < out_size)
        out[BB * TT + b] = bbs;
}

// ============ host launcher ============
extern "C" void kernel_launch(void* const* d_in, const int* in_sizes, int n_in,
                              void* d_out, int out_size)
{
    const float* enc = (const float*)d_in[0];
    const int*   lens = (const int*)d_in[1];
    const float* emb = (const float*)d_in[2];
    const float* Wq  = (const float*)d_in[3];
    const float* Wk  = (const float*)d_in[4];
    const float* Wfc = (const float*)d_in[5];
    const float* bfc = (const float*)d_in[6];

    float *p_encK, *p_h, *p_logits;
    cudaGetSymbolAddress((void**)&p_encK, g_encK);
    cudaGetSymbolAddress((void**)&p_h, g_h);
    cudaGetSymbolAddress((void**)&p_logits, g_logits);

    // encK = enc @ W_k   (8192 x 512 x 512)
    {
        dim3 grid(DD / GTN, (BB * SS) / GTM);
        gemm2_kernel<<<grid, 128>>>(enc, Wk, nullptr, p_encK, BB * SS, DD, DD);
    }

    // ---- step 1 (SOS for all rows) ----
    init_last_kernel<<<1, RR>>>();
    prep_kernel<<<RR, 512>>>(enc, lens, emb, Wq);
    {
        dim3 grid(VV / GTN, RR / GTM);
        gemm2_kernel<<<grid, 128>>>(p_h, Wfc, bfc, p_logits, RR, VV, DD);
    }
    top4_lse_kernel<<<RR, 512>>>();
    init_combine_kernel<<<BB, TT>>>();

    // ---- steps t = 2..63 ----
    for (int t = 2; t < TT; t++) {
        prep_kernel<<<RR, 512>>>(enc, lens, emb, Wq);
        {
            dim3 grid(VV / GTN, RR / GTM);
            gemm2_kernel<<<grid, 128>>>(p_h, Wfc, bfc, p_logits, RR, VV, DD);
        }
        top4_lse_kernel<<<RR, 512>>>();
        combine_kernel<<<BB, TT>>>(t, t & 1);
    }

    // after t=63 (odd), last combine wrote buffer 0
    finalize_kernel<<<BB, TT>>>((float*)d_out, out_size, 0);
}